// round 5
// baseline (speedup 1.0000x reference)
#include <cuda_runtime.h>
#include <cstdint>

// ---------------------------------------------------------------------------
// Problem constants
// ---------------------------------------------------------------------------
#define BB        4
#define LL        5000
#define HH        256
#define WW        256
#define HW        (HH * WW)          // 65536
#define C_IN      256
#define DIM_LOI   128
#define N_PTS0    32
#define N_PTS1    8
#define DIM_FC    1024
#define N_OUT     2500
#define NROWS     (BB * LL)          // 20000
#define NPAD      20096              // 157 * 128

// ---------------------------------------------------------------------------
// Static scratch (no allocations allowed)
// ---------------------------------------------------------------------------
__device__ float g_x[(size_t)BB * HW * DIM_LOI];      // fc1 out, pixel-major [b][hw][c]
__device__ float g_feat_h[(size_t)NPAD * DIM_FC];     // pooled features split hi/lo
__device__ float g_feat_l[(size_t)NPAD * DIM_FC];
__device__ float g_h1_h[(size_t)NPAD * DIM_FC];
__device__ float g_h1_l[(size_t)NPAD * DIM_FC];
__device__ float g_h2[(size_t)NPAD * DIM_FC];
__device__ float g_w1h[(size_t)DIM_FC * DIM_FC];
__device__ float g_w1l[(size_t)DIM_FC * DIM_FC];
__device__ float g_w2h[(size_t)DIM_FC * DIM_FC];
__device__ float g_w2l[(size_t)DIM_FC * DIM_FC];
__device__ float g_wfc1T[(size_t)C_IN * DIM_LOI];     // fc1_w transposed [k][n]
__device__ float g_s[(size_t)NROWS * 4];              // softmax scores
__device__ int   g_key[NROWS];
__device__ int   g_order[BB * LL];
__device__ int   g_cnt[BB];

// ---------------------------------------------------------------------------
// tf32 / cp.async helpers
// ---------------------------------------------------------------------------
__device__ __forceinline__ uint32_t tf32_hi(float a) {
    uint32_t r;
    asm("cvt.rna.tf32.f32 %0, %1;" : "=r"(r) : "f"(a));
    return r;
}
__device__ __forceinline__ void mma_tf32(float* c, const uint32_t* a, const uint32_t* b) {
    asm volatile(
        "mma.sync.aligned.m16n8k8.row.col.f32.tf32.tf32.f32 "
        "{%0,%1,%2,%3}, {%4,%5,%6,%7}, {%8,%9}, {%0,%1,%2,%3};"
        : "+f"(c[0]), "+f"(c[1]), "+f"(c[2]), "+f"(c[3])
        : "r"(a[0]), "r"(a[1]), "r"(a[2]), "r"(a[3]), "r"(b[0]), "r"(b[1]));
}
__device__ __forceinline__ void split2(float v, float& hi, float& lo) {
    uint32_t h = tf32_hi(v);
    hi = __uint_as_float(h);
    lo = __uint_as_float(tf32_hi(v - hi));
}
__device__ __forceinline__ uint32_t smem_u32(const void* p) {
    uint32_t a;
    asm("{ .reg .u64 t; cvta.to.shared.u64 t, %1; cvt.u32.u64 %0, t; }" : "=r"(a) : "l"(p));
    return a;
}
__device__ __forceinline__ void cp16(uint32_t dst, const void* src) {
    asm volatile("cp.async.cg.shared.global [%0], [%1], 16;"
                 :: "r"(dst), "l"(src) : "memory");
}
__device__ __forceinline__ void cp_commit() {
    asm volatile("cp.async.commit_group;" ::: "memory");
}
template<int N>
__device__ __forceinline__ void cp_wait() {
    asm volatile("cp.async.wait_group %0;" :: "n"(N) : "memory");
}

// ---------------------------------------------------------------------------
// Shared-memory geometry
// ---------------------------------------------------------------------------
#define ASTR 20     // smem A row stride (floats)
#define BSTR 136    // smem B row stride (floats)
#define ST_A  (128 * ASTR * 4)         // 10240 B
#define ST_B  (16 * BSTR * 4)          // 8704 B
#define STAGE (2 * ST_A + 2 * ST_B)    // 37888 B
#define NSTAGE 4
#define SMEM_MLP (NSTAGE * STAGE)      // 151552 B
#define SMEM_FC1 (2 * STAGE)           // 75776 B (fc1 keeps 2-stage reg loader)
// within a stage: Ahi @0, Alo @ST_A, Bhi @2*ST_A, Blo @2*ST_A+ST_B

// ---------------------------------------------------------------------------
// Warp-level 3xTF32 compute on a converted 128x16(k) stage.
// Warp tile 64x32: 4 mtiles(16) x 4 ntiles(8), k=16.
// ---------------------------------------------------------------------------
__device__ __forceinline__ void compute_stage(
    const float* __restrict__ Ahp, const float* __restrict__ Alp,
    const float* __restrict__ Bhp, const float* __restrict__ Blp,
    int warp_m, int warp_n, int gr, int tg, float acc[4][4][4])
{
#pragma unroll
    for (int kk = 0; kk < 16; kk += 8) {
        uint32_t ah[4][4], al[4][4], bh[4][2], bl[4][2];
#pragma unroll
        for (int mt = 0; mt < 4; mt++) {
            int r0 = (warp_m + mt * 16 + gr) * ASTR + kk + tg;
            int r1 = r0 + 8 * ASTR;
            ah[mt][0] = __float_as_uint(Ahp[r0]);
            ah[mt][1] = __float_as_uint(Ahp[r1]);
            ah[mt][2] = __float_as_uint(Ahp[r0 + 4]);
            ah[mt][3] = __float_as_uint(Ahp[r1 + 4]);
            al[mt][0] = __float_as_uint(Alp[r0]);
            al[mt][1] = __float_as_uint(Alp[r1]);
            al[mt][2] = __float_as_uint(Alp[r0 + 4]);
            al[mt][3] = __float_as_uint(Alp[r1 + 4]);
        }
#pragma unroll
        for (int nt = 0; nt < 4; nt++) {
            int c = warp_n + nt * 8 + gr;
            bh[nt][0] = __float_as_uint(Bhp[(kk + tg) * BSTR + c]);
            bh[nt][1] = __float_as_uint(Bhp[(kk + tg + 4) * BSTR + c]);
            bl[nt][0] = __float_as_uint(Blp[(kk + tg) * BSTR + c]);
            bl[nt][1] = __float_as_uint(Blp[(kk + tg + 4) * BSTR + c]);
        }
#pragma unroll
        for (int mt = 0; mt < 4; mt++)
#pragma unroll
            for (int nt = 0; nt < 4; nt++) {
                mma_tf32(acc[mt][nt], ah[mt], bh[nt]);
                mma_tf32(acc[mt][nt], ah[mt], bl[nt]);
                mma_tf32(acc[mt][nt], al[mt], bh[nt]);
            }
    }
}

__device__ __forceinline__ void store_f4_pair(float* hi_base, float* lo_base,
                                              int off, float4 v)
{
    float4 h, l;
    split2(v.x, h.x, l.x);
    split2(v.y, h.y, l.y);
    split2(v.z, h.z, l.z);
    split2(v.w, h.w, l.w);
    *(float4*)(hi_base + off) = h;
    *(float4*)(lo_base + off) = l;
}

// ---------------------------------------------------------------------------
// MLP GEMM (pre-split inputs, cp.async 4-stage pipeline):
//   C = relu(A @ W + bias),  A = Ah+Al (M x 1024), W = Wh+Wl ([k][n])
// SPLIT_OUT=1: write split hi/lo to C0/C1.  SPLIT_OUT=0: plain to C0.
// ---------------------------------------------------------------------------
template<int SPLIT_OUT>
__global__ __launch_bounds__(256, 1)
void gemm_mma3(const float* __restrict__ Ah_, const float* __restrict__ Al_,
               const float* __restrict__ Wh_, const float* __restrict__ Wl_,
               const float* __restrict__ bias,
               float* __restrict__ C0, float* __restrict__ C1)
{
    extern __shared__ __align__(16) char sm[];
    const uint32_t sb = smem_u32(sm);

    const int tid  = threadIdx.x;
    const int lane = tid & 31;
    const int wid  = tid >> 5;
    const int m0   = blockIdx.y * 128;
    const int n0   = blockIdx.x * 128;
    const int warp_m = (wid & 1) * 64;
    const int warp_n = (wid >> 1) * 32;
    const int gr = lane >> 2;
    const int tg = lane & 3;

    float acc[4][4][4];
#pragma unroll
    for (int mt = 0; mt < 4; mt++)
#pragma unroll
        for (int nt = 0; nt < 4; nt++)
#pragma unroll
            for (int r = 0; r < 4; r++) acc[mt][nt][r] = 0.f;

    const int a_m  = tid >> 2;
    const int a_ks = (tid & 3) << 2;
    const int b_k  = tid >> 5;
    const int b_n4 = (tid & 31) << 2;

    const float* Ah0 = Ah_ + (size_t)(m0 + a_m) * 1024 + a_ks;
    const float* Ah1 = Ah_ + (size_t)(m0 + a_m + 64) * 1024 + a_ks;
    const float* Al0 = Al_ + (size_t)(m0 + a_m) * 1024 + a_ks;
    const float* Al1 = Al_ + (size_t)(m0 + a_m + 64) * 1024 + a_ks;
    const float* Bh0 = Wh_ + (size_t)b_k * 1024 + n0 + b_n4;
    const float* Bh1 = Wh_ + (size_t)(b_k + 8) * 1024 + n0 + b_n4;
    const float* Bl0 = Wl_ + (size_t)b_k * 1024 + n0 + b_n4;
    const float* Bl1 = Wl_ + (size_t)(b_k + 8) * 1024 + n0 + b_n4;

    const uint32_t aoff0 = (uint32_t)(a_m * ASTR + a_ks) * 4;
    const uint32_t aoff1 = (uint32_t)((a_m + 64) * ASTR + a_ks) * 4;
    const uint32_t boff0 = (uint32_t)(b_k * BSTR + b_n4) * 4;
    const uint32_t boff1 = (uint32_t)((b_k + 8) * BSTR + b_n4) * 4;

    auto issue_chunk = [&](int ch) {
        const uint32_t st = sb + (uint32_t)(ch & (NSTAGE - 1)) * STAGE;
        const size_t ko = (size_t)ch * 16;
        cp16(st + aoff0, Ah0 + ko);
        cp16(st + aoff1, Ah1 + ko);
        cp16(st + ST_A + aoff0, Al0 + ko);
        cp16(st + ST_A + aoff1, Al1 + ko);
        cp16(st + 2 * ST_A + boff0, Bh0 + ko * 1024);
        cp16(st + 2 * ST_A + boff1, Bh1 + ko * 1024);
        cp16(st + 2 * ST_A + ST_B + boff0, Bl0 + ko * 1024);
        cp16(st + 2 * ST_A + ST_B + boff1, Bl1 + ko * 1024);
        cp_commit();
    };

    issue_chunk(0); issue_chunk(1); issue_chunk(2);

    for (int ch = 0; ch < 64; ch++) {
        cp_wait<2>();
        __syncthreads();
        if (ch + 3 < 64) issue_chunk(ch + 3);
        const char* st = sm + (ch & (NSTAGE - 1)) * STAGE;
        compute_stage((const float*)st, (const float*)(st + ST_A),
                      (const float*)(st + 2 * ST_A),
                      (const float*)(st + 2 * ST_A + ST_B),
                      warp_m, warp_n, gr, tg, acc);
    }

    // ---- epilogue: bias + relu (+ optional split)
#pragma unroll
    for (int mt = 0; mt < 4; mt++) {
        int row = m0 + warp_m + mt * 16 + gr;
#pragma unroll
        for (int nt = 0; nt < 4; nt++) {
            int col = n0 + warp_n + nt * 8 + tg * 2;
            float b0 = bias[col], b1 = bias[col + 1];
            float v00 = fmaxf(acc[mt][nt][0] + b0, 0.f);
            float v01 = fmaxf(acc[mt][nt][1] + b1, 0.f);
            float v10 = fmaxf(acc[mt][nt][2] + b0, 0.f);
            float v11 = fmaxf(acc[mt][nt][3] + b1, 0.f);
            size_t o0 = (size_t)row * 1024 + col;
            size_t o1 = (size_t)(row + 8) * 1024 + col;
            if (SPLIT_OUT) {
                float h, l; float2 H0, L0, H1, L1;
                split2(v00, h, l); H0.x = h; L0.x = l;
                split2(v01, h, l); H0.y = h; L0.y = l;
                split2(v10, h, l); H1.x = h; L1.x = l;
                split2(v11, h, l); H1.y = h; L1.y = l;
                *(float2*)(C0 + o0) = H0; *(float2*)(C1 + o0) = L0;
                *(float2*)(C0 + o1) = H1; *(float2*)(C1 + o1) = L1;
            } else {
                *(float2*)(C0 + o0) = make_float2(v00, v01);
                *(float2*)(C0 + o1) = make_float2(v10, v11);
            }
        }
    }
}

// ---------------------------------------------------------------------------
// fc1 GEMM (register loader, 2-stage, as in R4):
// x[b][hw][o] = feature[b][:][hw] . fc1_w[o][:] + fc1_b[o]
// ---------------------------------------------------------------------------
__global__ __launch_bounds__(256, 1)
void gemm_fc1(const float* __restrict__ feature, const float* __restrict__ Wt,
              const float* __restrict__ bias, float* __restrict__ X)
{
    extern __shared__ __align__(16) char sm[];

    const int tid  = threadIdx.x;
    const int lane = tid & 31;
    const int wid  = tid >> 5;
    const int b    = blockIdx.z;
    const int m0   = blockIdx.y * 128;
    const int warp_m = (wid & 1) * 64;
    const int warp_n = (wid >> 1) * 32;
    const int gr = lane >> 2;
    const int tg = lane & 3;

    const float* Ab = feature + (size_t)b * C_IN * HW;
    float* Cb = X + (size_t)b * HW * DIM_LOI;

    float acc[4][4][4];
#pragma unroll
    for (int mt = 0; mt < 4; mt++)
#pragma unroll
        for (int nt = 0; nt < 4; nt++)
#pragma unroll
            for (int r = 0; r < 4; r++) acc[mt][nt][r] = 0.f;

    const int a_m  = tid & 127;
    const int a_kh = (tid >> 7) << 3;
    const int b_k  = tid >> 5;
    const int b_n4 = (tid & 31) << 2;

    const float* Acol = Ab + (size_t)a_kh * HW + m0 + a_m;
    const float* Brow0 = Wt + (size_t)b_k * 128 + b_n4;
    const float* Brow1 = Wt + (size_t)(b_k + 8) * 128 + b_n4;

    float ra[8];
    float4 rb0, rb1;

    auto load_chunk = [&](int ch) {
        const size_t ko = (size_t)ch * 16;
#pragma unroll
        for (int j = 0; j < 8; j++)
            ra[j] = Acol[(ko + j) * HW];
        rb0 = *(const float4*)(Brow0 + ko * 128);
        rb1 = *(const float4*)(Brow1 + ko * 128);
    };
    auto store_chunk = [&](int p) {
        char* st = sm + p * STAGE;
        float* Ah = (float*)st;
        float* Al = (float*)(st + ST_A);
        float* Bh = (float*)(st + 2 * ST_A);
        float* Bl = (float*)(st + 2 * ST_A + ST_B);
        float4 v0 = make_float4(ra[0], ra[1], ra[2], ra[3]);
        float4 v1 = make_float4(ra[4], ra[5], ra[6], ra[7]);
        store_f4_pair(Ah, Al, a_m * ASTR + a_kh, v0);
        store_f4_pair(Ah, Al, a_m * ASTR + a_kh + 4, v1);
        store_f4_pair(Bh, Bl, b_k * BSTR + b_n4, rb0);
        store_f4_pair(Bh, Bl, (b_k + 8) * BSTR + b_n4, rb1);
    };
    auto compute_chunk = [&](int p) {
        const char* st = sm + p * STAGE;
        compute_stage((const float*)st, (const float*)(st + ST_A),
                      (const float*)(st + 2 * ST_A), (const float*)(st + 2 * ST_A + ST_B),
                      warp_m, warp_n, gr, tg, acc);
    };

    load_chunk(0);
    store_chunk(0);
    __syncthreads();

    for (int ch = 1; ch <= 16; ch++) {
        if (ch < 16) load_chunk(ch);
        compute_chunk((ch - 1) & 1);
        if (ch < 16) store_chunk(ch & 1);
        __syncthreads();
    }

#pragma unroll
    for (int mt = 0; mt < 4; mt++) {
        int row = m0 + warp_m + mt * 16 + gr;
#pragma unroll
        for (int nt = 0; nt < 4; nt++) {
            int col = warp_n + nt * 8 + tg * 2;
            float b0 = bias[col], b1 = bias[col + 1];
            float2 v0, v1;
            v0.x = acc[mt][nt][0] + b0;
            v0.y = acc[mt][nt][1] + b1;
            v1.x = acc[mt][nt][2] + b0;
            v1.y = acc[mt][nt][3] + b1;
            *(float2*)(Cb + (size_t)row * 128 + col) = v0;
            *(float2*)(Cb + (size_t)(row + 8) * 128 + col) = v1;
        }
    }
}

// ---------------------------------------------------------------------------
// Weight prep: fc1_w transpose; w1/w2 split into tf32 hi/lo
// ---------------------------------------------------------------------------
__global__ __launch_bounds__(256)
void transpose_fc1(const float* __restrict__ s, float* __restrict__ d)
{
    __shared__ float t[32][33];
    const int bx = blockIdx.x * 32;   // k
    const int by = blockIdx.y * 32;   // n
    const int tx = threadIdx.x, ty = threadIdx.y;
#pragma unroll
    for (int r = 0; r < 32; r += 8)
        t[ty + r][tx] = s[(size_t)(by + ty + r) * 256 + bx + tx];
    __syncthreads();
#pragma unroll
    for (int r = 0; r < 32; r += 8)
        d[(size_t)(bx + ty + r) * 128 + by + tx] = t[tx][ty + r];
}

__global__ __launch_bounds__(256)
void split_mat(const float* __restrict__ src, float* __restrict__ hi,
               float* __restrict__ lo, int n4)
{
    int i = blockIdx.x * blockDim.x + threadIdx.x;
    if (i >= n4) return;
    float4 v = ((const float4*)src)[i];
    float4 h, l;
    split2(v.x, h.x, l.x);
    split2(v.y, h.y, l.y);
    split2(v.z, h.z, l.z);
    split2(v.w, h.w, l.w);
    ((float4*)hi)[i] = h;
    ((float4*)lo)[i] = l;
}

// ---------------------------------------------------------------------------
// Bilinear sampling + maxpool -> split feature rows.
// ---------------------------------------------------------------------------
__global__ __launch_bounds__(128)
void sample_kernel(const float* __restrict__ lines,
                   float* __restrict__ fh, float* __restrict__ fl)
{
    const int bl = blockIdx.x;
    const int b  = bl / LL;
    const int c  = threadIdx.x;

    const float* xb = g_x + (size_t)b * HW * DIM_LOI;

    float4 ln = *(const float4*)(lines + (size_t)bl * 4);
    const float x0 = ln.x, y0 = ln.y, x1 = ln.z, y1 = ln.w;

    __shared__ float stage[DIM_LOI * N_PTS1];

    float maxv = 0.f;
#pragma unroll 4
    for (int pt = 0; pt < N_PTS0; pt++) {
        float lam = (float)pt * (1.0f / 31.0f);
        float px = x0 * lam + x1 * (1.0f - lam) - 0.5f;
        float py = y0 * lam + y1 * (1.0f - lam) - 0.5f;

        float px0 = fminf(fmaxf(floorf(px), 0.f), (float)(HH - 1));
        float py0 = fminf(fmaxf(floorf(py), 0.f), (float)(WW - 1));
        float px1 = fminf(px0 + 1.f, (float)(HH - 1));
        float py1 = fminf(py0 + 1.f, (float)(WW - 1));
        int ix0 = (int)px0, iy0 = (int)py0, ix1 = (int)px1, iy1 = (int)py1;

        float w00 = (px1 - px) * (py1 - py);
        float w10 = (px - px0) * (py1 - py);
        float w01 = (px1 - px) * (py - py0);
        float w11 = (px - px0) * (py - py0);

        const float* t00 = xb + (size_t)(ix0 * WW + iy0) * DIM_LOI + c;
        const float* t10 = xb + (size_t)(ix1 * WW + iy0) * DIM_LOI + c;
        const float* t01 = xb + (size_t)(ix0 * WW + iy1) * DIM_LOI + c;
        const float* t11 = xb + (size_t)(ix1 * WW + iy1) * DIM_LOI + c;
        float v = w00 * (*t00) + w10 * (*t10) + w01 * (*t01) + w11 * (*t11);

        if ((pt & 3) == 0) maxv = v; else maxv = fmaxf(maxv, v);
        if ((pt & 3) == 3) stage[c * N_PTS1 + (pt >> 2)] = maxv;
    }
    __syncthreads();

    float* fhr = fh + (size_t)bl * DIM_FC;
    float* flr = fl + (size_t)bl * DIM_FC;
    for (int i = c; i < DIM_FC; i += DIM_LOI) {
        float hi, lo;
        split2(stage[i], hi, lo);
        fhr[i] = hi;
        flr[i] = lo;
    }
}

// ---------------------------------------------------------------------------
// Final layer (1024 -> 4) + softmax + keep/key.
// ---------------------------------------------------------------------------
__global__ __launch_bounds__(128)
void layer3_kernel(const float* __restrict__ h2, const float* __restrict__ w3,
                   const float* __restrict__ b3)
{
    const int row = blockIdx.x;
    const int tid = threadIdx.x;
    const float* hr = h2 + (size_t)row * DIM_FC;

    float acc[4] = {0.f, 0.f, 0.f, 0.f};
    for (int k = tid; k < DIM_FC; k += 128) {
        float hv = hr[k];
        float4 wv = *(const float4*)(w3 + (size_t)k * 4);
        acc[0] += hv * wv.x; acc[1] += hv * wv.y;
        acc[2] += hv * wv.z; acc[3] += hv * wv.w;
    }
#pragma unroll
    for (int off = 16; off; off >>= 1)
#pragma unroll
        for (int n = 0; n < 4; n++)
            acc[n] += __shfl_down_sync(0xffffffffu, acc[n], off);

    __shared__ float red[4][4];
    if ((tid & 31) == 0)
#pragma unroll
        for (int n = 0; n < 4; n++) red[tid >> 5][n] = acc[n];
    __syncthreads();

    if (tid == 0) {
        float lg[4];
#pragma unroll
        for (int n = 0; n < 4; n++)
            lg[n] = red[0][n] + red[1][n] + red[2][n] + red[3][n] + b3[n];
        float mx = fmaxf(fmaxf(lg[0], lg[1]), fmaxf(lg[2], lg[3]));
        float e[4], sum = 0.f;
#pragma unroll
        for (int n = 0; n < 4; n++) { e[n] = __expf(lg[n] - mx); sum += e[n]; }
        float inv = 1.0f / sum;
        float s0 = e[0] * inv, s1 = e[1] * inv, s2 = e[2] * inv, s3 = e[3] * inv;
        float4 sv = {s0, s1, s2, s3};
        *(float4*)(g_s + (size_t)row * 4) = sv;

        bool keep = ((s1 > 0.25f) || (s2 > 0.25f) || (s3 > 0.25f)) && (s0 < 0.25f);
        int am = 0; float best = s0;
        if (s1 > best) { best = s1; am = 1; }
        if (s2 > best) { best = s2; am = 2; }
        if (s3 > best) { best = s3; am = 3; }
        g_key[row] = keep ? am : -1;
    }
}

// ---------------------------------------------------------------------------
// Stable counting sort by key desc (buckets 3,2,1). One block per batch.
// ---------------------------------------------------------------------------
__global__ __launch_bounds__(1024)
void select_kernel()
{
    const int b = blockIdx.x;
    const int t = threadIdx.x;
    const int* key = g_key + b * LL;

    __shared__ int sc[3][1024];

    const int l0 = t * 5;
    const int l1 = min(l0 + 5, LL);
    int n1 = 0, n2 = 0, n3 = 0;
    for (int i = l0; i < l1; i++) {
        int k = key[i];
        n1 += (k == 1); n2 += (k == 2); n3 += (k == 3);
    }
    sc[0][t] = n1; sc[1][t] = n2; sc[2][t] = n3;
    __syncthreads();

    for (int off = 1; off < 1024; off <<= 1) {
        int v0 = (t >= off) ? sc[0][t - off] : 0;
        int v1 = (t >= off) ? sc[1][t - off] : 0;
        int v2 = (t >= off) ? sc[2][t - off] : 0;
        __syncthreads();
        sc[0][t] += v0; sc[1][t] += v1; sc[2][t] += v2;
        __syncthreads();
    }

    const int T1 = sc[0][1023], T2 = sc[1][1023], T3 = sc[2][1023];
    int p3 = sc[2][t] - n3;
    int p2 = T3 + (sc[1][t] - n2);
    int p1 = T3 + T2 + (sc[0][t] - n1);

    int* ord = g_order + b * LL;
    for (int i = l0; i < l1; i++) {
        int k = key[i];
        if (k == 3)      ord[p3++] = i;
        else if (k == 2) ord[p2++] = i;
        else if (k == 1) ord[p1++] = i;
    }
    if (t == 0) g_cnt[b] = T1 + T2 + T3;
}

// ---------------------------------------------------------------------------
// Output writer
// ---------------------------------------------------------------------------
__global__ void out_writer(const float* __restrict__ lines,
                           float* __restrict__ out, int out_size)
{
    const int gid = blockIdx.x * blockDim.x + threadIdx.x;

    if (gid < BB * N_OUT) {
        int b = gid / N_OUT, r = gid - b * N_OUT;
        int cnt = g_cnt[b];
        float4 lo = {0.f, 0.f, 0.f, 0.f};
        float4 so = {0.f, 0.f, 0.f, 0.f};
        if (cnt > 0) {
            int idx = g_order[b * LL + (r % cnt)];
            lo = *(const float4*)(lines + (size_t)(b * LL + idx) * 4);
            so = *(const float4*)(g_s + (size_t)(b * LL + idx) * 4);
        }
        *(float4*)(out + (size_t)gid * 4) = lo;
        if (out_size >= 2 * 4 * BB * N_OUT)
            *(float4*)(out + (size_t)(BB * N_OUT + gid) * 4) = so;
    }
    int g2 = gid - BB * N_OUT;
    if (g2 >= 0 && g2 < NROWS && out_size >= 8 * BB * N_OUT + 4 * NROWS) {
        *(float4*)(out + (size_t)(2 * BB * N_OUT + g2) * 4) =
            *(const float4*)(g_s + (size_t)g2 * 4);
    }
}

// ---------------------------------------------------------------------------
// Launch
// ---------------------------------------------------------------------------
extern "C" void kernel_launch(void* const* d_in, const int* in_sizes, int n_in,
                              void* d_out, int out_size)
{
    const float* feature = (const float*)d_in[0];
    const float* lines   = (const float*)d_in[1];
    const float* fc1_w   = (const float*)d_in[2];
    const float* fc1_b   = (const float*)d_in[3];
    const float* w1      = (const float*)d_in[4];
    const float* b1      = (const float*)d_in[5];
    const float* w2      = (const float*)d_in[6];
    const float* b2      = (const float*)d_in[7];
    const float* w3      = (const float*)d_in[8];
    const float* b3      = (const float*)d_in[9];
    float* out = (float*)d_out;

    float *x_p, *fh_p, *fl_p, *h1h_p, *h1l_p, *h2_p, *wt_p;
    float *w1h_p, *w1l_p, *w2h_p, *w2l_p;
    cudaGetSymbolAddress((void**)&x_p,   g_x);
    cudaGetSymbolAddress((void**)&fh_p,  g_feat_h);
    cudaGetSymbolAddress((void**)&fl_p,  g_feat_l);
    cudaGetSymbolAddress((void**)&h1h_p, g_h1_h);
    cudaGetSymbolAddress((void**)&h1l_p, g_h1_l);
    cudaGetSymbolAddress((void**)&h2_p,  g_h2);
    cudaGetSymbolAddress((void**)&wt_p,  g_wfc1T);
    cudaGetSymbolAddress((void**)&w1h_p, g_w1h);
    cudaGetSymbolAddress((void**)&w1l_p, g_w1l);
    cudaGetSymbolAddress((void**)&w2h_p, g_w2h);
    cudaGetSymbolAddress((void**)&w2l_p, g_w2l);

    cudaFuncSetAttribute(gemm_mma3<0>, cudaFuncAttributeMaxDynamicSharedMemorySize,
                         SMEM_MLP);
    cudaFuncSetAttribute(gemm_mma3<1>, cudaFuncAttributeMaxDynamicSharedMemorySize,
                         SMEM_MLP);
    cudaFuncSetAttribute(gemm_fc1, cudaFuncAttributeMaxDynamicSharedMemorySize,
                         SMEM_FC1);

    // weight prep
    transpose_fc1<<<dim3(8, 4), dim3(32, 8)>>>(fc1_w, wt_p);
    split_mat<<<1024, 256>>>(w1, w1h_p, w1l_p, DIM_FC * DIM_FC / 4);
    split_mat<<<1024, 256>>>(w2, w2h_p, w2l_p, DIM_FC * DIM_FC / 4);

    // fc1 on tensor cores
    gemm_fc1<<<dim3(1, HW / 128, BB), 256, SMEM_FC1>>>(feature, wt_p, fc1_b, x_p);

    // bilinear sample + maxpool -> split feat
    sample_kernel<<<NROWS, DIM_LOI>>>(lines, fh_p, fl_p);

    // MLP layers 1 & 2 (cp.async pipelined 3xTF32)
    gemm_mma3<1><<<dim3(8, NPAD / 128), 256, SMEM_MLP>>>(
        fh_p, fl_p, w1h_p, w1l_p, b1, h1h_p, h1l_p);
    gemm_mma3<0><<<dim3(8, NPAD / 128), 256, SMEM_MLP>>>(
        h1h_p, h1l_p, w2h_p, w2l_p, b2, h2_p, nullptr);

    // final layer + softmax + keep/key
    layer3_kernel<<<NROWS, 128>>>(h2_p, w3, b3);

    // stable bucket sort per batch
    select_kernel<<<BB, 1024>>>();

    // outputs
    int tot = BB * N_OUT + NROWS;
    out_writer<<<(tot + 255) / 256, 256>>>(lines, out, out_size);
}

// round 6
// speedup vs baseline: 1.2075x; 1.2075x over previous
#include <cuda_runtime.h>
#include <cstdint>

// ---------------------------------------------------------------------------
// Problem constants
// ---------------------------------------------------------------------------
#define BB        4
#define LL        5000
#define HH        256
#define WW        256
#define HW        (HH * WW)          // 65536
#define C_IN      256
#define DIM_LOI   128
#define N_PTS0    32
#define N_PTS1    8
#define DIM_FC    1024
#define N_OUT     2500
#define NROWS     (BB * LL)          // 20000
#define NPAD      20096              // 157 * 128

// ---------------------------------------------------------------------------
// Static scratch (no allocations allowed)
// ---------------------------------------------------------------------------
__device__ float g_x[(size_t)BB * HW * DIM_LOI];      // fc1 out, pixel-major [b][hw][c]
__device__ float g_feat[(size_t)NPAD * DIM_FC];       // pooled features (pad rows stay 0)
__device__ float g_h1[(size_t)NPAD * DIM_FC];
__device__ float g_h2[(size_t)NPAD * DIM_FC];
__device__ float g_wfc1T[(size_t)C_IN * DIM_LOI];     // fc1_w transposed [k][n]
__device__ float g_s[(size_t)NROWS * 4];              // softmax scores
__device__ int   g_key[NROWS];
__device__ int   g_order[BB * LL];
__device__ int   g_cnt[BB];

// ---------------------------------------------------------------------------
// tf32 helpers
// ---------------------------------------------------------------------------
__device__ __forceinline__ uint32_t tf32_hi(float a) {
    uint32_t r;
    asm("cvt.rna.tf32.f32 %0, %1;" : "=r"(r) : "f"(a));
    return r;
}
__device__ __forceinline__ void mma_tf32(float* c, const uint32_t* a, const uint32_t* b) {
    asm volatile(
        "mma.sync.aligned.m16n8k8.row.col.f32.tf32.tf32.f32 "
        "{%0,%1,%2,%3}, {%4,%5,%6,%7}, {%8,%9}, {%0,%1,%2,%3};"
        : "+f"(c[0]), "+f"(c[1]), "+f"(c[2]), "+f"(c[3])
        : "r"(a[0]), "r"(a[1]), "r"(a[2]), "r"(a[3]), "r"(b[0]), "r"(b[1]));
}
__device__ __forceinline__ void split2(float v, float& hi, float& lo) {
    uint32_t h = tf32_hi(v);
    hi = __uint_as_float(h);
    lo = __uint_as_float(tf32_hi(v - hi));
}
__device__ __forceinline__ uint32_t smem_u32(const void* p) {
    uint32_t a;
    asm("{ .reg .u64 t; cvta.to.shared.u64 t, %1; cvt.u32.u64 %0, t; }" : "=r"(a) : "l"(p));
    return a;
}
__device__ __forceinline__ void ldsm4(uint32_t r[4], uint32_t addr) {
    asm volatile("ldmatrix.sync.aligned.m8n8.x4.shared.b16 {%0,%1,%2,%3}, [%4];"
                 : "=r"(r[0]), "=r"(r[1]), "=r"(r[2]), "=r"(r[3]) : "r"(addr));
}

// ---------------------------------------------------------------------------
// Shared-memory geometry (double-buffered converted tiles)
// ---------------------------------------------------------------------------
#define ASTR 20     // smem A row stride (floats)
#define BSTR 136    // smem B row stride (floats)
#define ST_A  (128 * ASTR * 4)         // 10240 B
#define ST_B  (16 * BSTR * 4)          // 8704 B
#define STAGE (2 * ST_A + 2 * ST_B)    // 37888 B
#define SMEM_BYTES (2 * STAGE)         // 75776 B
// within a stage: Ahi @0, Alo @ST_A, Bhi @2*ST_A, Blo @2*ST_A+ST_B

// ---------------------------------------------------------------------------
// Warp-level 3xTF32 compute on a converted 128x16(k) stage.
// A fragments via ldmatrix.x4 (layout As[m][k], ASTR stride is LDSM-compatible:
// every 8x4-float subtile row is 16B aligned, row stride 80B = conflict-free).
// AhU/AlU: per-thread byte addresses of this thread's LDSM lane row at warp_m.
// ---------------------------------------------------------------------------
__device__ __forceinline__ void compute_stage(
    uint32_t AhU, uint32_t AlU,
    const float* __restrict__ Bhp, const float* __restrict__ Blp,
    int warp_n, int gr, int tg, float acc[4][4][4])
{
#pragma unroll
    for (int kk = 0; kk < 16; kk += 8) {
        uint32_t bh[4][2], bl[4][2];
#pragma unroll
        for (int nt = 0; nt < 4; nt++) {
            int c = warp_n + nt * 8 + gr;
            bh[nt][0] = __float_as_uint(Bhp[(kk + tg) * BSTR + c]);
            bh[nt][1] = __float_as_uint(Bhp[(kk + tg + 4) * BSTR + c]);
            bl[nt][0] = __float_as_uint(Blp[(kk + tg) * BSTR + c]);
            bl[nt][1] = __float_as_uint(Blp[(kk + tg + 4) * BSTR + c]);
        }
#pragma unroll
        for (int mt = 0; mt < 4; mt++) {
            uint32_t ah[4], al[4];
            const uint32_t off = (uint32_t)(mt * 16 * ASTR + kk) * 4;
            ldsm4(ah, AhU + off);
            ldsm4(al, AlU + off);
#pragma unroll
            for (int nt = 0; nt < 4; nt++) {
                mma_tf32(acc[mt][nt], ah, bh[nt]);
                mma_tf32(acc[mt][nt], ah, bl[nt]);
                mma_tf32(acc[mt][nt], al, bh[nt]);
            }
        }
    }
}

__device__ __forceinline__ void store_f4_pair(float* hi_base, float* lo_base,
                                              int off, float4 v)
{
    float4 h, l;
    split2(v.x, h.x, l.x);
    split2(v.y, h.y, l.y);
    split2(v.z, h.z, l.z);
    split2(v.w, h.w, l.w);
    *(float4*)(hi_base + off) = h;
    *(float4*)(lo_base + off) = l;
}

// LDSM lane offset (in floats) within the A tile:
//   matrix = lane>>3; row = (matrix&1)*8 + (lane&7); col = (matrix>>1)*4
__device__ __forceinline__ int ldsm_lane_off(int lane) {
    int row = (((lane >> 3) & 1) << 3) + (lane & 7);
    int col = (lane >> 4) << 2;
    return row * ASTR + col;
}

// ---------------------------------------------------------------------------
// MLP GEMM: C[M,1024] = relu(A[M,1024] @ W[1024,1024] + bias)
// A row-major, W row-major [k][n]. Block tile 128x128, 256 thr, dbl-buffered.
// ---------------------------------------------------------------------------
__global__ __launch_bounds__(256, 2)
void gemm_mma3(const float* __restrict__ A, const float* __restrict__ W,
               const float* __restrict__ bias, float* __restrict__ C)
{
    extern __shared__ __align__(16) char sm[];

    const int tid  = threadIdx.x;
    const int lane = tid & 31;
    const int wid  = tid >> 5;
    const int m0   = blockIdx.y * 128;
    const int n0   = blockIdx.x * 128;
    const int warp_m = (wid & 1) * 64;
    const int warp_n = (wid >> 1) * 32;
    const int gr = lane >> 2;
    const int tg = lane & 3;
    const int laneOff = ldsm_lane_off(lane);
    const uint32_t AU0 = smem_u32(sm) + 4u * (uint32_t)(warp_m * ASTR + laneOff);

    float acc[4][4][4];
#pragma unroll
    for (int mt = 0; mt < 4; mt++)
#pragma unroll
        for (int nt = 0; nt < 4; nt++)
#pragma unroll
            for (int r = 0; r < 4; r++) acc[mt][nt][r] = 0.f;

    const int a_m  = tid >> 2;
    const int a_ks = (tid & 3) << 2;
    const int b_k  = tid >> 5;
    const int b_n4 = (tid & 31) << 2;

    const float* Arow0 = A + (size_t)(m0 + a_m) * 1024 + a_ks;
    const float* Arow1 = A + (size_t)(m0 + a_m + 64) * 1024 + a_ks;
    const float* Brow0 = W + (size_t)b_k * 1024 + n0 + b_n4;
    const float* Brow1 = W + (size_t)(b_k + 8) * 1024 + n0 + b_n4;

    float4 ra0, ra1, rb0, rb1;

    auto load_chunk = [&](int ch) {
        const size_t ko = (size_t)ch * 16;
        ra0 = *(const float4*)(Arow0 + ko);
        ra1 = *(const float4*)(Arow1 + ko);
        rb0 = *(const float4*)(Brow0 + ko * 1024);
        rb1 = *(const float4*)(Brow1 + ko * 1024);
    };
    auto store_chunk = [&](int p) {
        char* st = sm + p * STAGE;
        float* Ah = (float*)st;
        float* Al = (float*)(st + ST_A);
        float* Bh = (float*)(st + 2 * ST_A);
        float* Bl = (float*)(st + 2 * ST_A + ST_B);
        store_f4_pair(Ah, Al, a_m * ASTR + a_ks, ra0);
        store_f4_pair(Ah, Al, (a_m + 64) * ASTR + a_ks, ra1);
        store_f4_pair(Bh, Bl, b_k * BSTR + b_n4, rb0);
        store_f4_pair(Bh, Bl, (b_k + 8) * BSTR + b_n4, rb1);
    };
    auto compute_chunk = [&](int p) {
        const char* st = sm + p * STAGE;
        compute_stage(AU0 + (uint32_t)(p * STAGE), AU0 + (uint32_t)(p * STAGE + ST_A),
                      (const float*)(st + 2 * ST_A),
                      (const float*)(st + 2 * ST_A + ST_B),
                      warp_n, gr, tg, acc);
    };

    load_chunk(0);
    store_chunk(0);
    __syncthreads();

    for (int ch = 1; ch <= 64; ch++) {
        if (ch < 64) load_chunk(ch);
        compute_chunk((ch - 1) & 1);
        if (ch < 64) store_chunk(ch & 1);
        __syncthreads();
    }

    // ---- epilogue: bias + relu
#pragma unroll
    for (int mt = 0; mt < 4; mt++) {
        int row = m0 + warp_m + mt * 16 + gr;
#pragma unroll
        for (int nt = 0; nt < 4; nt++) {
            int col = n0 + warp_n + nt * 8 + tg * 2;
            float b0 = bias[col], b1 = bias[col + 1];
            float2 v0, v1;
            v0.x = fmaxf(acc[mt][nt][0] + b0, 0.f);
            v0.y = fmaxf(acc[mt][nt][1] + b1, 0.f);
            v1.x = fmaxf(acc[mt][nt][2] + b0, 0.f);
            v1.y = fmaxf(acc[mt][nt][3] + b1, 0.f);
            *(float2*)(C + (size_t)row * 1024 + col) = v0;
            *(float2*)(C + (size_t)(row + 8) * 1024 + col) = v1;
        }
    }
}

// ---------------------------------------------------------------------------
// fc1 GEMM: x[b][hw][o] = feature[b][:][hw] . fc1_w[o][:] + fc1_b[o]
// A K-major: A(m=hw, k=c) at feature[b][k][hw]. B = g_wfc1T [k][n], n=128.
// ---------------------------------------------------------------------------
__global__ __launch_bounds__(256, 2)
void gemm_fc1(const float* __restrict__ feature, const float* __restrict__ Wt,
              const float* __restrict__ bias, float* __restrict__ X)
{
    extern __shared__ __align__(16) char sm[];

    const int tid  = threadIdx.x;
    const int lane = tid & 31;
    const int wid  = tid >> 5;
    const int b    = blockIdx.z;
    const int m0   = blockIdx.y * 128;
    const int warp_m = (wid & 1) * 64;
    const int warp_n = (wid >> 1) * 32;
    const int gr = lane >> 2;
    const int tg = lane & 3;
    const int laneOff = ldsm_lane_off(lane);
    const uint32_t AU0 = smem_u32(sm) + 4u * (uint32_t)(warp_m * ASTR + laneOff);

    const float* Ab = feature + (size_t)b * C_IN * HW;
    float* Cb = X + (size_t)b * HW * DIM_LOI;

    float acc[4][4][4];
#pragma unroll
    for (int mt = 0; mt < 4; mt++)
#pragma unroll
        for (int nt = 0; nt < 4; nt++)
#pragma unroll
            for (int r = 0; r < 4; r++) acc[mt][nt][r] = 0.f;

    const int a_m  = tid & 127;
    const int a_kh = (tid >> 7) << 3;
    const int b_k  = tid >> 5;
    const int b_n4 = (tid & 31) << 2;

    const float* Acol = Ab + (size_t)a_kh * HW + m0 + a_m;
    const float* Brow0 = Wt + (size_t)b_k * 128 + b_n4;
    const float* Brow1 = Wt + (size_t)(b_k + 8) * 128 + b_n4;

    float ra[8];
    float4 rb0, rb1;

    auto load_chunk = [&](int ch) {
        const size_t ko = (size_t)ch * 16;
#pragma unroll
        for (int j = 0; j < 8; j++)
            ra[j] = Acol[(ko + j) * HW];
        rb0 = *(const float4*)(Brow0 + ko * 128);
        rb1 = *(const float4*)(Brow1 + ko * 128);
    };
    auto store_chunk = [&](int p) {
        char* st = sm + p * STAGE;
        float* Ah = (float*)st;
        float* Al = (float*)(st + ST_A);
        float* Bh = (float*)(st + 2 * ST_A);
        float* Bl = (float*)(st + 2 * ST_A + ST_B);
        float4 v0 = make_float4(ra[0], ra[1], ra[2], ra[3]);
        float4 v1 = make_float4(ra[4], ra[5], ra[6], ra[7]);
        store_f4_pair(Ah, Al, a_m * ASTR + a_kh, v0);
        store_f4_pair(Ah, Al, a_m * ASTR + a_kh + 4, v1);
        store_f4_pair(Bh, Bl, b_k * BSTR + b_n4, rb0);
        store_f4_pair(Bh, Bl, (b_k + 8) * BSTR + b_n4, rb1);
    };
    auto compute_chunk = [&](int p) {
        const char* st = sm + p * STAGE;
        compute_stage(AU0 + (uint32_t)(p * STAGE), AU0 + (uint32_t)(p * STAGE + ST_A),
                      (const float*)(st + 2 * ST_A),
                      (const float*)(st + 2 * ST_A + ST_B),
                      warp_n, gr, tg, acc);
    };

    load_chunk(0);
    store_chunk(0);
    __syncthreads();

    for (int ch = 1; ch <= 16; ch++) {
        if (ch < 16) load_chunk(ch);
        compute_chunk((ch - 1) & 1);
        if (ch < 16) store_chunk(ch & 1);
        __syncthreads();
    }

#pragma unroll
    for (int mt = 0; mt < 4; mt++) {
        int row = m0 + warp_m + mt * 16 + gr;
#pragma unroll
        for (int nt = 0; nt < 4; nt++) {
            int col = warp_n + nt * 8 + tg * 2;
            float b0 = bias[col], b1 = bias[col + 1];
            float2 v0, v1;
            v0.x = acc[mt][nt][0] + b0;
            v0.y = acc[mt][nt][1] + b1;
            v1.x = acc[mt][nt][2] + b0;
            v1.y = acc[mt][nt][3] + b1;
            *(float2*)(Cb + (size_t)row * 128 + col) = v0;
            *(float2*)(Cb + (size_t)(row + 8) * 128 + col) = v1;
        }
    }
}

// ---------------------------------------------------------------------------
// fc1_w [128][256] -> Wt [256][128]
// ---------------------------------------------------------------------------
__global__ __launch_bounds__(256)
void transpose_fc1(const float* __restrict__ s, float* __restrict__ d)
{
    __shared__ float t[32][33];
    const int bx = blockIdx.x * 32;   // k
    const int by = blockIdx.y * 32;   // n
    const int tx = threadIdx.x, ty = threadIdx.y;
#pragma unroll
    for (int r = 0; r < 32; r += 8)
        t[ty + r][tx] = s[(size_t)(by + ty + r) * 256 + bx + tx];
    __syncthreads();
#pragma unroll
    for (int r = 0; r < 32; r += 8)
        d[(size_t)(bx + ty + r) * 128 + by + tx] = t[tx][ty + r];
}

// ---------------------------------------------------------------------------
// Bilinear sampling + maxpool. One block per line, thread = channel.
// ---------------------------------------------------------------------------
__global__ __launch_bounds__(128)
void sample_kernel(const float* __restrict__ lines, float* __restrict__ feat)
{
    const int bl = blockIdx.x;
    const int b  = bl / LL;
    const int c  = threadIdx.x;

    const float* xb = g_x + (size_t)b * HW * DIM_LOI;

    float4 ln = *(const float4*)(lines + (size_t)bl * 4);
    const float x0 = ln.x, y0 = ln.y, x1 = ln.z, y1 = ln.w;

    __shared__ float stage[DIM_LOI * N_PTS1];

    float maxv = 0.f;
#pragma unroll 4
    for (int pt = 0; pt < N_PTS0; pt++) {
        float lam = (float)pt * (1.0f / 31.0f);
        float px = x0 * lam + x1 * (1.0f - lam) - 0.5f;
        float py = y0 * lam + y1 * (1.0f - lam) - 0.5f;

        float px0 = fminf(fmaxf(floorf(px), 0.f), (float)(HH - 1));
        float py0 = fminf(fmaxf(floorf(py), 0.f), (float)(WW - 1));
        float px1 = fminf(px0 + 1.f, (float)(HH - 1));
        float py1 = fminf(py0 + 1.f, (float)(WW - 1));
        int ix0 = (int)px0, iy0 = (int)py0, ix1 = (int)px1, iy1 = (int)py1;

        float w00 = (px1 - px) * (py1 - py);
        float w10 = (px - px0) * (py1 - py);
        float w01 = (px1 - px) * (py - py0);
        float w11 = (px - px0) * (py - py0);

        const float* t00 = xb + (size_t)(ix0 * WW + iy0) * DIM_LOI + c;
        const float* t10 = xb + (size_t)(ix1 * WW + iy0) * DIM_LOI + c;
        const float* t01 = xb + (size_t)(ix0 * WW + iy1) * DIM_LOI + c;
        const float* t11 = xb + (size_t)(ix1 * WW + iy1) * DIM_LOI + c;
        float v = w00 * (*t00) + w10 * (*t10) + w01 * (*t01) + w11 * (*t11);

        if ((pt & 3) == 0) maxv = v; else maxv = fmaxf(maxv, v);
        if ((pt & 3) == 3) stage[c * N_PTS1 + (pt >> 2)] = maxv;
    }
    __syncthreads();

    float* frow = feat + (size_t)bl * DIM_FC;
    for (int i = c; i < DIM_FC; i += DIM_LOI) frow[i] = stage[i];
}

// ---------------------------------------------------------------------------
// Final layer (1024 -> 4) + softmax + keep/key.
// ---------------------------------------------------------------------------
__global__ __launch_bounds__(128)
void layer3_kernel(const float* __restrict__ h2, const float* __restrict__ w3,
                   const float* __restrict__ b3)
{
    const int row = blockIdx.x;
    const int tid = threadIdx.x;
    const float* hr = h2 + (size_t)row * DIM_FC;

    float acc[4] = {0.f, 0.f, 0.f, 0.f};
    for (int k = tid; k < DIM_FC; k += 128) {
        float hv = hr[k];
        float4 wv = *(const float4*)(w3 + (size_t)k * 4);
        acc[0] += hv * wv.x; acc[1] += hv * wv.y;
        acc[2] += hv * wv.z; acc[3] += hv * wv.w;
    }
#pragma unroll
    for (int off = 16; off; off >>= 1)
#pragma unroll
        for (int n = 0; n < 4; n++)
            acc[n] += __shfl_down_sync(0xffffffffu, acc[n], off);

    __shared__ float red[4][4];
    if ((tid & 31) == 0)
#pragma unroll
        for (int n = 0; n < 4; n++) red[tid >> 5][n] = acc[n];
    __syncthreads();

    if (tid == 0) {
        float lg[4];
#pragma unroll
        for (int n = 0; n < 4; n++)
            lg[n] = red[0][n] + red[1][n] + red[2][n] + red[3][n] + b3[n];
        float mx = fmaxf(fmaxf(lg[0], lg[1]), fmaxf(lg[2], lg[3]));
        float e[4], sum = 0.f;
#pragma unroll
        for (int n = 0; n < 4; n++) { e[n] = __expf(lg[n] - mx); sum += e[n]; }
        float inv = 1.0f / sum;
        float s0 = e[0] * inv, s1 = e[1] * inv, s2 = e[2] * inv, s3 = e[3] * inv;
        float4 sv = {s0, s1, s2, s3};
        *(float4*)(g_s + (size_t)row * 4) = sv;

        bool keep = ((s1 > 0.25f) || (s2 > 0.25f) || (s3 > 0.25f)) && (s0 < 0.25f);
        int am = 0; float best = s0;
        if (s1 > best) { best = s1; am = 1; }
        if (s2 > best) { best = s2; am = 2; }
        if (s3 > best) { best = s3; am = 3; }
        g_key[row] = keep ? am : -1;
    }
}

// ---------------------------------------------------------------------------
// Stable counting sort by key desc (buckets 3,2,1). One block per batch.
// ---------------------------------------------------------------------------
__global__ __launch_bounds__(1024)
void select_kernel()
{
    const int b = blockIdx.x;
    const int t = threadIdx.x;
    const int* key = g_key + b * LL;

    __shared__ int sc[3][1024];

    const int l0 = t * 5;
    const int l1 = min(l0 + 5, LL);
    int n1 = 0, n2 = 0, n3 = 0;
    for (int i = l0; i < l1; i++) {
        int k = key[i];
        n1 += (k == 1); n2 += (k == 2); n3 += (k == 3);
    }
    sc[0][t] = n1; sc[1][t] = n2; sc[2][t] = n3;
    __syncthreads();

    for (int off = 1; off < 1024; off <<= 1) {
        int v0 = (t >= off) ? sc[0][t - off] : 0;
        int v1 = (t >= off) ? sc[1][t - off] : 0;
        int v2 = (t >= off) ? sc[2][t - off] : 0;
        __syncthreads();
        sc[0][t] += v0; sc[1][t] += v1; sc[2][t] += v2;
        __syncthreads();
    }

    const int T1 = sc[0][1023], T2 = sc[1][1023], T3 = sc[2][1023];
    int p3 = sc[2][t] - n3;
    int p2 = T3 + (sc[1][t] - n2);
    int p1 = T3 + T2 + (sc[0][t] - n1);

    int* ord = g_order + b * LL;
    for (int i = l0; i < l1; i++) {
        int k = key[i];
        if (k == 3)      ord[p3++] = i;
        else if (k == 2) ord[p2++] = i;
        else if (k == 1) ord[p1++] = i;
    }
    if (t == 0) g_cnt[b] = T1 + T2 + T3;
}

// ---------------------------------------------------------------------------
// Output writer
// ---------------------------------------------------------------------------
__global__ void out_writer(const float* __restrict__ lines,
                           float* __restrict__ out, int out_size)
{
    const int gid = blockIdx.x * blockDim.x + threadIdx.x;

    if (gid < BB * N_OUT) {
        int b = gid / N_OUT, r = gid - b * N_OUT;
        int cnt = g_cnt[b];
        float4 lo = {0.f, 0.f, 0.f, 0.f};
        float4 so = {0.f, 0.f, 0.f, 0.f};
        if (cnt > 0) {
            int idx = g_order[b * LL + (r % cnt)];
            lo = *(const float4*)(lines + (size_t)(b * LL + idx) * 4);
            so = *(const float4*)(g_s + (size_t)(b * LL + idx) * 4);
        }
        *(float4*)(out + (size_t)gid * 4) = lo;
        if (out_size >= 2 * 4 * BB * N_OUT)
            *(float4*)(out + (size_t)(BB * N_OUT + gid) * 4) = so;
    }
    int g2 = gid - BB * N_OUT;
    if (g2 >= 0 && g2 < NROWS && out_size >= 8 * BB * N_OUT + 4 * NROWS) {
        *(float4*)(out + (size_t)(2 * BB * N_OUT + g2) * 4) =
            *(const float4*)(g_s + (size_t)g2 * 4);
    }
}

// ---------------------------------------------------------------------------
// Launch
// ---------------------------------------------------------------------------
extern "C" void kernel_launch(void* const* d_in, const int* in_sizes, int n_in,
                              void* d_out, int out_size)
{
    const float* feature = (const float*)d_in[0];
    const float* lines   = (const float*)d_in[1];
    const float* fc1_w   = (const float*)d_in[2];
    const float* fc1_b   = (const float*)d_in[3];
    const float* w1      = (const float*)d_in[4];
    const float* b1      = (const float*)d_in[5];
    const float* w2      = (const float*)d_in[6];
    const float* b2      = (const float*)d_in[7];
    const float* w3      = (const float*)d_in[8];
    const float* b3      = (const float*)d_in[9];
    float* out = (float*)d_out;

    float *x_p, *feat_p, *h1_p, *h2_p, *wt_p;
    cudaGetSymbolAddress((void**)&x_p,    g_x);
    cudaGetSymbolAddress((void**)&feat_p, g_feat);
    cudaGetSymbolAddress((void**)&h1_p,   g_h1);
    cudaGetSymbolAddress((void**)&h2_p,   g_h2);
    cudaGetSymbolAddress((void**)&wt_p,   g_wfc1T);

    cudaFuncSetAttribute(gemm_mma3, cudaFuncAttributeMaxDynamicSharedMemorySize,
                         SMEM_BYTES);
    cudaFuncSetAttribute(gemm_fc1, cudaFuncAttributeMaxDynamicSharedMemorySize,
                         SMEM_BYTES);

    // fc1_w -> [k][n]
    transpose_fc1<<<dim3(8, 4), dim3(32, 8)>>>(fc1_w, wt_p);

    // fc1 on tensor cores
    gemm_fc1<<<dim3(1, HW / 128, BB), 256, SMEM_BYTES>>>(feature, wt_p, fc1_b, x_p);

    // bilinear sample + maxpool -> feat
    sample_kernel<<<NROWS, DIM_LOI>>>(lines, feat_p);

    // MLP layers 1 & 2 (3xTF32 mma, ldmatrix A fragments, 2 CTAs/SM)
    gemm_mma3<<<dim3(8, NPAD / 128), 256, SMEM_BYTES>>>(feat_p, w1, b1, h1_p);
    gemm_mma3<<<dim3(8, NPAD / 128), 256, SMEM_BYTES>>>(h1_p, w2, b2, h2_p);

    // final layer + softmax + keep/key
    layer3_kernel<<<NROWS, 128>>>(h2_p, w3, b3);

    // stable bucket sort per batch
    select_kernel<<<BB, 1024>>>();

    // outputs
    int tot = BB * N_OUT + NROWS;
    out_writer<<<(tot + 255) / 256, 256>>>(lines, out, out_size);
}